// round 1
// baseline (speedup 1.0000x reference)
#include <cuda_runtime.h>

#define NTREE 64
#define NPT   3280
#define NINT  1093      // internal nodes per tree = OFF[7]
#define NLEAF 2187
#define CD    8
#define GD    8
#define GH    4         // g's per CTA
#define MS    128
#define TPB   256

// Scratch (static device arrays: allocation-free per harness rules)
__device__ float g_beta [(size_t)NTREE * NPT  * 64];   // [node][g][c]
__device__ float g_tbeta[(size_t)NTREE * NINT * 64];   // internal nodes only
__device__ float g_w    [(size_t)NTREE * NINT * 64];   // eps/t_beta, internal only

__device__ __forceinline__ int get_x(const void* xr, bool is64, size_t idx) {
    return is64 ? (int)((const long long*)xr)[idx] : ((const int*)xr)[idx];
}

__global__ __launch_bounds__(TPB)
void phtmm_kernel(const float* __restrict__ lamA, const float* __restrict__ lamB,
                  const float* __restrict__ lamPi, const float* __restrict__ lamSP,
                  const void* __restrict__ xraw, float* __restrict__ out)
{
    constexpr int OFFS[9] = {0,1,4,13,40,121,364,1093,3280};

    __shared__ __align__(16) float sASP[3][CD][GH][CD];  // SP*softmax(A)  [b][c'][gl][c]
    __shared__ __align__(16) float sA2 [3][CD][GH][CD];  // SP*A*log(A)
    __shared__ __align__(16) float sBm [MS][GH][CD];     // softmax(B)     [m][gl][c]
    __shared__ __align__(16) float sPi [3][GH][CD];
    __shared__ __align__(16) float sLPi[3][GH][CD];      // log softmax(Pi)
    __shared__ float sLSP[3][GH];                        // log softmax(SP)
    __shared__ float sEll[GH];

    const int tid   = threadIdx.x;
    const int t     = blockIdx.y;          // tree
    const int gbase = blockIdx.x * GH;     // g-half base
    const int gl    = tid & 3;             // fixed per thread (TPB % 4 == 0)

    // ---- x dtype sniff: int64 iff OR of first 8 qwords is in [0, MS) ----
    bool is64;
    {
        const long long* p = (const long long*)xraw;
        long long m = p[0] | p[1] | p[2] | p[3] | p[4] | p[5] | p[6] | p[7];
        is64 = ((unsigned long long)m < (unsigned long long)MS);
    }

    if (tid < GH) sEll[tid] = 0.f;

    // ================= parameter softmaxes into smem =================
    // SP log-softmax (over b), 12 entries
    for (int i = tid; i < 3*GH; i += TPB) {
        int b = i >> 2, gg = gbase + (i & 3);
        float v0 = lamSP[gg], v1 = lamSP[GD+gg], v2 = lamSP[2*GD+gg];
        float mx = fmaxf(v0, fmaxf(v1, v2));
        float den = expf(v0-mx) + expf(v1-mx) + expf(v2-mx);
        float vb = (b==0) ? v0 : ((b==1) ? v1 : v2);
        sLSP[b][i & 3] = (vb - mx) - logf(den);
    }
    // A softmax over c for each (c', b, g); fold SP in. 96 columns.
    for (int i = tid; i < CD*3*GH; i += TPB) {
        int glc = i & 3; int b = (i >> 2) % 3; int cp = i / 12;
        int gg = gbase + glc;
        float v0 = lamSP[gg], v1 = lamSP[GD+gg], v2 = lamSP[2*GD+gg];
        float smx = fmaxf(v0, fmaxf(v1, v2));
        float e0 = expf(v0-smx), e1 = expf(v1-smx), e2 = expf(v2-smx);
        float sp = ((b==0) ? e0 : ((b==1) ? e1 : e2)) / (e0+e1+e2);
        float a[CD]; float mx = -1e30f;
        #pragma unroll
        for (int c = 0; c < CD; c++) { a[c] = lamA[((c*CD+cp)*3+b)*GD + gg]; mx = fmaxf(mx, a[c]); }
        float den = 0.f;
        #pragma unroll
        for (int c = 0; c < CD; c++) den += expf(a[c]-mx);
        float ld = logf(den), inv = 1.f/den;
        #pragma unroll
        for (int c = 0; c < CD; c++) {
            float soft = expf(a[c]-mx) * inv;
            float lg   = (a[c]-mx) - ld;
            sASP[b][cp][glc][c] = sp * soft;
            sA2 [b][cp][glc][c] = sp * soft * lg;
        }
    }
    // B softmax over m for each (c,g); 32 rows of 128
    for (int i = tid; i < CD*GH; i += TPB) {
        int glc = i & 3; int c = i >> 2; int gg = gbase + glc;
        const float* base = lamB + (size_t)c * MS * GD + gg;
        float mx = -1e30f;
        for (int m = 0; m < MS; m++) mx = fmaxf(mx, base[(size_t)m*GD]);
        float den = 0.f;
        for (int m = 0; m < MS; m++) den += expf(base[(size_t)m*GD]-mx);
        float inv = 1.f/den;
        for (int m = 0; m < MS; m++) sBm[m][glc][c] = expf(base[(size_t)m*GD]-mx) * inv;
    }
    // Pi softmax over c for each (b,g); 12 columns
    for (int i = tid; i < 3*GH; i += TPB) {
        int glc = i & 3; int b = i >> 2; int gg = gbase + glc;
        float a[CD]; float mx = -1e30f;
        #pragma unroll
        for (int c = 0; c < CD; c++) { a[c] = lamPi[(c*3+b)*GD + gg]; mx = fmaxf(mx, a[c]); }
        float den = 0.f;
        #pragma unroll
        for (int c = 0; c < CD; c++) den += expf(a[c]-mx);
        float ld = logf(den), inv = 1.f/den;
        #pragma unroll
        for (int c = 0; c < CD; c++) {
            sPi [b][glc][c] = expf(a[c]-mx) * inv;
            sLPi[b][glc][c] = (a[c]-mx) - ld;
        }
    }
    __syncthreads();

    const size_t xoff = (size_t)t * NPT;

    // ================= upward pass: leaves =================
    for (int i = tid; i < NLEAF*GH; i += TPB) {
        int n = NINT + (i >> 2);
        int b = (n - NINT) % 3;
        int xv = get_x(xraw, is64, xoff + n);
        const float* pi = &sPi[b][gl][0];
        const float* bm = &sBm[xv][gl][0];
        float v[CD]; float s = 0.f;
        #pragma unroll
        for (int c = 0; c < CD; c++) { v[c] = pi[c]*bm[c]; s += v[c]; }
        float inv = __fdividef(1.f, s);
        float* bp = &g_beta[((size_t)t*NPT + n)*64 + (size_t)(gbase+gl)*8];
        reinterpret_cast<float4*>(bp)[0] = make_float4(v[0]*inv, v[1]*inv, v[2]*inv, v[3]*inv);
        reinterpret_cast<float4*>(bp)[1] = make_float4(v[4]*inv, v[5]*inv, v[6]*inv, v[7]*inv);
    }
    __syncthreads();

    // ================= upward pass: levels d=7..1, compute parents at d-1 ====
    #pragma unroll
    for (int d = 7; d >= 1; --d) {
        const int p0 = OFFS[d-1], c0 = OFFS[d];
        const int np = OFFS[d] - p0;
        for (int i = tid; i < np*GH; i += TPB) {
            int p  = p0 + (i >> 2);
            int cb = c0 + 3*(p - p0);
            float acc[CD] = {0,0,0,0,0,0,0,0};
            #pragma unroll
            for (int b = 0; b < 3; b++) {
                const float* bp = &g_beta[((size_t)t*NPT + cb + b)*64 + (size_t)(gbase+gl)*8];
                float4 x0 = reinterpret_cast<const float4*>(bp)[0];
                float4 x1 = reinterpret_cast<const float4*>(bp)[1];
                float bc[CD] = {x0.x,x0.y,x0.z,x0.w,x1.x,x1.y,x1.z,x1.w};
                #pragma unroll
                for (int cp = 0; cp < CD; cp++) {
                    float v = bc[cp];
                    const float* ap = &sASP[b][cp][gl][0];
                    #pragma unroll
                    for (int c = 0; c < CD; c++) acc[c] = fmaf(ap[c], v, acc[c]);
                }
            }
            float* tp = &g_tbeta[((size_t)t*NINT + p)*64 + (size_t)(gbase+gl)*8];
            reinterpret_cast<float4*>(tp)[0] = make_float4(acc[0],acc[1],acc[2],acc[3]);
            reinterpret_cast<float4*>(tp)[1] = make_float4(acc[4],acc[5],acc[6],acc[7]);
            int xv = get_x(xraw, is64, xoff + p);
            const float* bm = &sBm[xv][gl][0];
            float bu[CD]; float s = 0.f;
            #pragma unroll
            for (int c = 0; c < CD; c++) { bu[c] = acc[c]*bm[c]; s += bu[c]; }
            float inv = __fdividef(1.f, s);
            float* bp = &g_beta[((size_t)t*NPT + p)*64 + (size_t)(gbase+gl)*8];
            reinterpret_cast<float4*>(bp)[0] = make_float4(bu[0]*inv,bu[1]*inv,bu[2]*inv,bu[3]*inv);
            reinterpret_cast<float4*>(bp)[1] = make_float4(bu[4]*inv,bu[5]*inv,bu[6]*inv,bu[7]*inv);
        }
        __syncthreads();
    }

    // ================= downward pass =================
    float ell_acc = 0.f;
    // root: eps = beta; w = beta/t_beta; Bm ell term
    if (tid < GH) {
        int g = gbase + tid;
        const float* bp = &g_beta [(size_t)t*NPT *64 + (size_t)g*8];
        const float* tp = &g_tbeta[(size_t)t*NINT*64 + (size_t)g*8];
        float*       wp = &g_w    [(size_t)t*NINT*64 + (size_t)g*8];
        int xv = get_x(xraw, is64, xoff);
        const float* bm = &sBm[xv][tid][0];
        #pragma unroll
        for (int c = 0; c < CD; c++) {
            float bv = bp[c];
            wp[c] = __fdividef(bv, tp[c]);
            ell_acc = fmaf(bv, bm[c], ell_acc);
        }
    }
    __syncthreads();

    #pragma unroll
    for (int d = 1; d <= 7; ++d) {
        const int p0 = OFFS[d-1], c0 = OFFS[d];
        const int np = OFFS[d] - p0;
        for (int i = tid; i < np*GH; i += TPB) {
            int p = p0 + (i >> 2);
            const float* wp = &g_w[((size_t)t*NINT + p)*64 + (size_t)(gbase+gl)*8];
            float4 w0 = reinterpret_cast<const float4*>(wp)[0];
            float4 w1 = reinterpret_cast<const float4*>(wp)[1];
            float w[CD] = {w0.x,w0.y,w0.z,w0.w,w1.x,w1.y,w1.z,w1.w};
            int cb = c0 + 3*(p - p0);
            #pragma unroll
            for (int b = 0; b < 3; b++) {
                int ch = cb + b;
                const float* bp = &g_beta[((size_t)t*NPT + ch)*64 + (size_t)(gbase+gl)*8];
                float4 b0 = reinterpret_cast<const float4*>(bp)[0];
                float4 b1 = reinterpret_cast<const float4*>(bp)[1];
                float bc[CD] = {b0.x,b0.y,b0.z,b0.w,b1.x,b1.y,b1.z,b1.w};
                int xv = get_x(xraw, is64, xoff + ch);
                const float* bm = &sBm[xv][gl][0];
                float eps[CD]; float se = 0.f, ebm = 0.f, s2 = 0.f;
                #pragma unroll
                for (int cp = 0; cp < CD; cp++) {
                    const float* ap = &sASP[b][cp][gl][0];
                    const float* a2 = &sA2 [b][cp][gl][0];
                    float t1 = 0.f, t2 = 0.f;
                    #pragma unroll
                    for (int c = 0; c < CD; c++) {
                        t1 = fmaf(ap[c], w[c], t1);
                        t2 = fmaf(a2[c], w[c], t2);
                    }
                    float e = bc[cp] * t1;         // eps[ch][cp]
                    eps[cp] = e;
                    se  += e;
                    ebm  = fmaf(e, bm[cp], ebm);   // eps * Bm[:, x[ch]]
                    s2   = fmaf(bc[cp], t2, s2);   // sum ej*logA
                }
                ell_acc += s2 + se * sLSP[b][gl] + ebm;
                if (d == 7) {                       // leaf: + eps*logPi
                    const float* lp = &sLPi[b][gl][0];
                    #pragma unroll
                    for (int cp = 0; cp < CD; cp++) ell_acc = fmaf(eps[cp], lp[cp], ell_acc);
                } else {                            // internal: store w = eps/t_beta
                    const float* tp = &g_tbeta[((size_t)t*NINT + ch)*64 + (size_t)(gbase+gl)*8];
                    float*       wo = &g_w    [((size_t)t*NINT + ch)*64 + (size_t)(gbase+gl)*8];
                    float wv[CD];
                    #pragma unroll
                    for (int cp = 0; cp < CD; cp++) wv[cp] = __fdividef(eps[cp], tp[cp]);
                    reinterpret_cast<float4*>(wo)[0] = make_float4(wv[0],wv[1],wv[2],wv[3]);
                    reinterpret_cast<float4*>(wo)[1] = make_float4(wv[4],wv[5],wv[6],wv[7]);
                }
            }
        }
        __syncthreads();
    }

    // ================= reduce ell over threads, write output =================
    float v = ell_acc;
    v += __shfl_down_sync(0xffffffffu, v, 16);
    v += __shfl_down_sync(0xffffffffu, v, 8);
    v += __shfl_down_sync(0xffffffffu, v, 4);
    if ((tid & 31) < 4) atomicAdd(&sEll[tid & 3], v);
    __syncthreads();
    if (tid < GH) out[t*GD + gbase + tid] = -sEll[tid];
}

extern "C" void kernel_launch(void* const* d_in, const int* in_sizes, int n_in,
                              void* d_out, int out_size) {
    // inputs: 0 lam_A, 1 lam_B, 2 lam_Pi, 3 lam_SP, 4 x, 5 pos, 6 leaves, 7 batch
    dim3 grid(2, NTREE);   // (g-half, tree)
    phtmm_kernel<<<grid, TPB>>>((const float*)d_in[0], (const float*)d_in[1],
                                (const float*)d_in[2], (const float*)d_in[3],
                                d_in[4], (float*)d_out);
}

// round 3
// speedup vs baseline: 1.3644x; 1.3644x over previous
#include <cuda_runtime.h>

#define NTREE 64
#define NPT   3280
#define NINT  1093
#define CD    8
#define GD    8
#define MS    128
#define TPB   256
#define NS    12          // padded node stride in floats (48B, bank-conflict-free)

// smem layout (floats)
#define OFF_TW    (NINT*NS)              // 13116
#define OFF_BM    (2*NINT*NS)            // 26232
#define OFF_ASP   (OFF_BM + MS*CD)       // 27256
#define OFF_A2    (OFF_ASP + 3*CD*CD)    // 27448
#define OFF_PI    (OFF_A2  + 3*CD*CD)    // 27640
#define OFF_LPI   (OFF_PI  + 3*CD)       // 27664
#define OFF_RED   (OFF_LPI + 3*CD)       // 27688
#define SMEM_FLOATS (OFF_RED + 8)        // 27696
#define SMEM_BYTES  (SMEM_FLOATS * 4)    // 110784

__device__ __forceinline__ int get_x(const void* xr, bool is64, size_t idx) {
    return is64 ? (int)((const long long*)xr)[idx] : ((const int*)xr)[idx];
}

__device__ __forceinline__ void ld8(const float* p, float* v) {
    float4 a = reinterpret_cast<const float4*>(p)[0];
    float4 b = reinterpret_cast<const float4*>(p)[1];
    v[0]=a.x; v[1]=a.y; v[2]=a.z; v[3]=a.w; v[4]=b.x; v[5]=b.y; v[6]=b.z; v[7]=b.w;
}
__device__ __forceinline__ void st8(float* p, const float* v) {
    reinterpret_cast<float4*>(p)[0] = make_float4(v[0],v[1],v[2],v[3]);
    reinterpret_cast<float4*>(p)[1] = make_float4(v[4],v[5],v[6],v[7]);
}

__global__ __launch_bounds__(TPB, 2)
void phtmm_kernel(const float* __restrict__ lamA, const float* __restrict__ lamB,
                  const float* __restrict__ lamPi, const float* __restrict__ lamSP,
                  const void* __restrict__ xraw, float* __restrict__ out)
{
    extern __shared__ __align__(16) float sm[];
    float* sBeta = sm;                 // internal-node beta   [node][NS]
    float* sTW   = sm + OFF_TW;        // t_beta, overwritten in place by w
    float* sBm   = sm + OFF_BM;        // softmax(B)[m][c]
    float* sASP  = sm + OFF_ASP;       // SP*A        [b][cp][c]
    float* sA2   = sm + OFF_A2;        // SP*A*logA   [b][cp][c]
    float* sPi   = sm + OFF_PI;        // Pi          [b][c]
    float* sLPi  = sm + OFF_LPI;       // log Pi      [b][c]
    float* sRed  = sm + OFF_RED;

    const int tid  = threadIdx.x;
    const int g    = blockIdx.x;       // 0..7
    const int t    = blockIdx.y;       // tree
    const int lane = tid & 31;
    const int wid  = tid >> 5;

    // ---- x dtype sniff (int64 iff OR of first 8 qwords < MS) ----
    bool is64;
    {
        const long long* p = (const long long*)xraw;
        long long m = p[0]|p[1]|p[2]|p[3]|p[4]|p[5]|p[6]|p[7];
        is64 = ((unsigned long long)m < (unsigned long long)MS);
    }

    // ---- SP softmax (registers, every thread) ----
    float lsp[3];
    {
        float v0 = lamSP[g], v1 = lamSP[GD+g], v2 = lamSP[2*GD+g];
        float mx = fmaxf(v0, fmaxf(v1, v2));
        float e0 = __expf(v0-mx), e1 = __expf(v1-mx), e2 = __expf(v2-mx);
        float ld = __logf(e0+e1+e2);
        lsp[0] = (v0-mx)-ld; lsp[1] = (v1-mx)-ld; lsp[2] = (v2-mx)-ld;
    }

    // ---- B softmax: warp w handles c = w, lanes over m ----
    {
        const float* bb = lamB + (size_t)wid * MS * GD + g;
        float v[4];
        float mx = -1e30f;
        #pragma unroll
        for (int j = 0; j < 4; j++) { v[j] = bb[(size_t)(lane + 32*j)*GD]; mx = fmaxf(mx, v[j]); }
        #pragma unroll
        for (int o = 16; o >= 1; o >>= 1) mx = fmaxf(mx, __shfl_xor_sync(0xffffffffu, mx, o));
        float e[4]; float den = 0.f;
        #pragma unroll
        for (int j = 0; j < 4; j++) { e[j] = __expf(v[j]-mx); den += e[j]; }
        #pragma unroll
        for (int o = 16; o >= 1; o >>= 1) den += __shfl_xor_sync(0xffffffffu, den, o);
        float inv = __fdividef(1.f, den);
        #pragma unroll
        for (int j = 0; j < 4; j++) sBm[(lane + 32*j)*CD + wid] = e[j]*inv;
    }

    // ---- A softmax over c, fold SP. 24 columns (b, cp) ----
    if (tid < 24) {
        int b = tid % 3, cp = tid / 3;
        float sp = __expf(lsp[b]);
        float a[CD]; float mx = -1e30f;
        #pragma unroll
        for (int c = 0; c < CD; c++) { a[c] = lamA[((c*CD+cp)*3+b)*GD + g]; mx = fmaxf(mx, a[c]); }
        float den = 0.f;
        #pragma unroll
        for (int c = 0; c < CD; c++) den += __expf(a[c]-mx);
        float ld = __logf(den), inv = __fdividef(1.f, den);
        #pragma unroll
        for (int c = 0; c < CD; c++) {
            float soft = __expf(a[c]-mx) * inv;
            float lg   = (a[c]-mx) - ld;
            sASP[(b*CD+cp)*CD + c] = sp * soft;
            sA2 [(b*CD+cp)*CD + c] = sp * soft * lg;
        }
    } else if (tid < 27) {                 // ---- Pi softmax, 3 columns ----
        int b = tid - 24;
        float a[CD]; float mx = -1e30f;
        #pragma unroll
        for (int c = 0; c < CD; c++) { a[c] = lamPi[(c*3+b)*GD + g]; mx = fmaxf(mx, a[c]); }
        float den = 0.f;
        #pragma unroll
        for (int c = 0; c < CD; c++) den += __expf(a[c]-mx);
        float ld = __logf(den), inv = __fdividef(1.f, den);
        #pragma unroll
        for (int c = 0; c < CD; c++) {
            sPi [b*CD + c] = __expf(a[c]-mx) * inv;
            sLPi[b*CD + c] = (a[c]-mx) - ld;
        }
    }
    __syncthreads();

    const size_t xoff = (size_t)t * NPT;

    // ================= upward: level 7 (leaf children computed on the fly) ====
    for (int p = 364 + tid; p < 1093; p += TPB) {
        float acc[CD] = {0,0,0,0,0,0,0,0};
        int cb = 1093 + 3*(p - 364);
        #pragma unroll
        for (int b = 0; b < 3; b++) {
            int xv = get_x(xraw, is64, xoff + cb + b);
            float bm[CD]; ld8(sBm + xv*CD, bm);
            const float* pi = sPi + b*CD;
            float v[CD]; float s = 0.f;
            #pragma unroll
            for (int c = 0; c < CD; c++) { v[c] = pi[c]*bm[c]; s += v[c]; }
            float inv = __fdividef(1.f, s);
            #pragma unroll
            for (int cp = 0; cp < CD; cp++) {
                float bcv = v[cp]*inv;
                const float* ap = sASP + (b*CD+cp)*CD;
                #pragma unroll
                for (int c = 0; c < CD; c++) acc[c] = fmaf(ap[c], bcv, acc[c]);
            }
        }
        st8(sTW + p*NS, acc);
        int xv = get_x(xraw, is64, xoff + p);
        float bm[CD]; ld8(sBm + xv*CD, bm);
        float s = 0.f;
        #pragma unroll
        for (int c = 0; c < CD; c++) { acc[c] *= bm[c]; s += acc[c]; }
        float inv = __fdividef(1.f, s);
        #pragma unroll
        for (int c = 0; c < CD; c++) acc[c] *= inv;
        st8(sBeta + p*NS, acc);
    }
    __syncthreads();

    // ================= upward: levels 6..1 =================
    {
        int p0 = 121, p1 = 364;
        #pragma unroll 1
        for (int d = 6; d >= 1; --d) {
            for (int p = p0 + tid; p < p1; p += TPB) {
                float acc[CD] = {0,0,0,0,0,0,0,0};
                int cb = p1 + 3*(p - p0);
                #pragma unroll
                for (int b = 0; b < 3; b++) {
                    float bc[CD]; ld8(sBeta + (cb+b)*NS, bc);
                    #pragma unroll
                    for (int cp = 0; cp < CD; cp++) {
                        float bcv = bc[cp];
                        const float* ap = sASP + (b*CD+cp)*CD;
                        #pragma unroll
                        for (int c = 0; c < CD; c++) acc[c] = fmaf(ap[c], bcv, acc[c]);
                    }
                }
                st8(sTW + p*NS, acc);
                int xv = get_x(xraw, is64, xoff + p);
                float bm[CD]; ld8(sBm + xv*CD, bm);
                float s = 0.f;
                #pragma unroll
                for (int c = 0; c < CD; c++) { acc[c] *= bm[c]; s += acc[c]; }
                float inv = __fdividef(1.f, s);
                #pragma unroll
                for (int c = 0; c < CD; c++) acc[c] *= inv;
                st8(sBeta + p*NS, acc);
            }
            p1 = p0; p0 = (p0 - 1) / 3;
            __syncthreads();
        }
    }

    // ================= downward =================
    float ell = 0.f;
    if (tid == 0) {   // root: w = beta/t_beta (in place), ell += beta.Bm[x0]
        int xv = get_x(xraw, is64, xoff);
        const float* bm = sBm + xv*CD;
        #pragma unroll
        for (int c = 0; c < CD; c++) {
            float bv = sBeta[c];
            ell = fmaf(bv, bm[c], ell);
            sTW[c] = __fdividef(bv, sTW[c]);
        }
    }
    __syncthreads();

    // levels 1..6 (children internal)
    {
        int p0 = 0, p1 = 1;
        #pragma unroll 1
        for (int d = 1; d <= 6; ++d) {
            for (int p = p0 + tid; p < p1; p += TPB) {
                float w[CD]; ld8(sTW + p*NS, w);
                int cb = p1 + 3*(p - p0);
                #pragma unroll
                for (int b = 0; b < 3; b++) {
                    int ch = cb + b;
                    float bc[CD]; ld8(sBeta + ch*NS, bc);
                    int xv = get_x(xraw, is64, xoff + ch);
                    float bm[CD]; ld8(sBm + xv*CD, bm);
                    float eps[CD]; float se = 0.f, ebm = 0.f, s2 = 0.f;
                    #pragma unroll
                    for (int cp = 0; cp < CD; cp++) {
                        const float* ap = sASP + (b*CD+cp)*CD;
                        const float* a2 = sA2  + (b*CD+cp)*CD;
                        float t1 = 0.f, t2 = 0.f;
                        #pragma unroll
                        for (int c = 0; c < CD; c++) {
                            t1 = fmaf(ap[c], w[c], t1);
                            t2 = fmaf(a2[c], w[c], t2);
                        }
                        float e = bc[cp] * t1;
                        eps[cp] = e;
                        se += e;
                        ebm = fmaf(e, bm[cp], ebm);
                        s2  = fmaf(bc[cp], t2, s2);
                    }
                    ell += s2 + se*lsp[b] + ebm;
                    float tb[CD]; ld8(sTW + ch*NS, tb);
                    float wv[CD];
                    #pragma unroll
                    for (int cp = 0; cp < CD; cp++) wv[cp] = __fdividef(eps[cp], tb[cp]);
                    st8(sTW + ch*NS, wv);
                }
            }
            p0 = p1; p1 = 3*p1 + 1;
            __syncthreads();
        }
    }

    // level 7 (children are leaves; beta recomputed, + logPi term)
    for (int p = 364 + tid; p < 1093; p += TPB) {
        float w[CD]; ld8(sTW + p*NS, w);
        int cb = 1093 + 3*(p - 364);
        #pragma unroll
        for (int b = 0; b < 3; b++) {
            int ch = cb + b;
            int xv = get_x(xraw, is64, xoff + ch);
            float bm[CD]; ld8(sBm + xv*CD, bm);
            const float* pi = sPi + b*CD;
            float bc[CD]; float s = 0.f;
            #pragma unroll
            for (int c = 0; c < CD; c++) { bc[c] = pi[c]*bm[c]; s += bc[c]; }
            float inv = __fdividef(1.f, s);
            #pragma unroll
            for (int c = 0; c < CD; c++) bc[c] *= inv;
            const float* lp = sLPi + b*CD;
            float se = 0.f, ebm = 0.f, s2 = 0.f, elp = 0.f;
            #pragma unroll
            for (int cp = 0; cp < CD; cp++) {
                const float* ap = sASP + (b*CD+cp)*CD;
                const float* a2 = sA2  + (b*CD+cp)*CD;
                float t1 = 0.f, t2 = 0.f;
                #pragma unroll
                for (int c = 0; c < CD; c++) {
                    t1 = fmaf(ap[c], w[c], t1);
                    t2 = fmaf(a2[c], w[c], t2);
                }
                float e = bc[cp] * t1;
                se += e;
                ebm = fmaf(e, bm[cp], ebm);
                s2  = fmaf(bc[cp], t2, s2);
                elp = fmaf(e, lp[cp], elp);
            }
            ell += s2 + se*lsp[b] + ebm + elp;
        }
    }

    // ================= reduce + write =================
    #pragma unroll
    for (int o = 16; o >= 1; o >>= 1) ell += __shfl_down_sync(0xffffffffu, ell, o);
    if (lane == 0) sRed[wid] = ell;
    __syncthreads();
    if (tid == 0) {
        float s = 0.f;
        #pragma unroll
        for (int wI = 0; wI < 8; wI++) s += sRed[wI];
        out[t*GD + g] = -s;
    }
}

extern "C" void kernel_launch(void* const* d_in, const int* in_sizes, int n_in,
                              void* d_out, int out_size) {
    // inputs: 0 lam_A, 1 lam_B, 2 lam_Pi, 3 lam_SP, 4 x, 5 pos, 6 leaves, 7 batch
    cudaFuncSetAttribute(phtmm_kernel, cudaFuncAttributeMaxDynamicSharedMemorySize, SMEM_BYTES);
    dim3 grid(GD, NTREE);   // (g, tree) = 512 CTAs
    phtmm_kernel<<<grid, TPB, SMEM_BYTES>>>((const float*)d_in[0], (const float*)d_in[1],
                                            (const float*)d_in[2], (const float*)d_in[3],
                                            d_in[4], (float*)d_out);
}